// round 16
// baseline (speedup 1.0000x reference)
#include <cuda_runtime.h>

// Fixed shapes: B=8, H=8, S=16384, Dv=64, d_k=1
#define BH      64
#define SEQ     16384
#define DV      64
#define NSPLIT  16
#define CHUNK   (SEQ / NSPLIT)   // 1024 rows per split
#define PSTRIDE 68               // 64 ktv + ksq + qsq, padded to float4 stride

__device__ float g_part[BH * NSPLIT * PSTRIDE];

// ---------------------------------------------------------------------------
// Kernel 1: per-(bh, split) partial reduction (~44us @ LTS chip cap).
//   ktv_part[e] = sum_{s in chunk} K[s] * V[s, e];  + ||K||^2, ||Q||^2 partials
//   K chunk staged in smem; 2 independent __ldcs float4 loads per body,
//   unroll 4 -> 8 loads in flight; dual accumulators.
// ---------------------------------------------------------------------------
__global__ __launch_bounds__(256) void reduce_kernel(
    const float* __restrict__ Q,
    const float* __restrict__ K,
    const float* __restrict__ V)
{
    const int bh    = blockIdx.x / NSPLIT;
    const int split = blockIdx.x % NSPLIT;
    const int t     = threadIdx.x;
    const int colg  = t & 15;   // which float4 of the 64-wide V row
    const int rowg  = t >> 4;   // row offset within a 16-row step

    const float4* __restrict__ Vp4 =
        reinterpret_cast<const float4*>(V + (size_t)bh * SEQ * DV + (size_t)(split * CHUNK) * DV);
    const float4* __restrict__ Kp4 =
        reinterpret_cast<const float4*>(K + bh * SEQ + split * CHUNK);
    const float4* __restrict__ Qp4 =
        reinterpret_cast<const float4*>(Q + bh * SEQ + split * CHUNK);

    __shared__ float sK[CHUNK];

    // Cooperative stage of K chunk + uniform ksq/qsq partials (1 float4 each).
    float4 kv = Kp4[t];
    reinterpret_cast<float4*>(sK)[t] = kv;
    float ksq = kv.x * kv.x + kv.y * kv.y + kv.z * kv.z + kv.w * kv.w;
    float4 qv = Qp4[t];
    float qsq = qv.x * qv.x + qv.y * qv.y + qv.z * qv.z + qv.w * qv.w;
    __syncthreads();

    float4 a0 = make_float4(0.f, 0.f, 0.f, 0.f);
    float4 a1 = make_float4(0.f, 0.f, 0.f, 0.f);

    #pragma unroll 4
    for (int r = rowg; r < CHUNK; r += 32) {
        float  k0 = sK[r];
        float4 v0 = __ldcs(&Vp4[(size_t)r * 16 + colg]);
        float  k1 = sK[r + 16];
        float4 v1 = __ldcs(&Vp4[(size_t)(r + 16) * 16 + colg]);
        a0.x += k0 * v0.x;  a0.y += k0 * v0.y;  a0.z += k0 * v0.z;  a0.w += k0 * v0.w;
        a1.x += k1 * v1.x;  a1.y += k1 * v1.y;  a1.z += k1 * v1.z;  a1.w += k1 * v1.w;
    }
    a0.x += a1.x; a0.y += a1.y; a0.z += a1.z; a0.w += a1.w;

    // Fold the two row-groups within each warp (lane ^ 16 has same colg).
    a0.x += __shfl_xor_sync(0xFFFFFFFFu, a0.x, 16);
    a0.y += __shfl_xor_sync(0xFFFFFFFFu, a0.y, 16);
    a0.z += __shfl_xor_sync(0xFFFFFFFFu, a0.z, 16);
    a0.w += __shfl_xor_sync(0xFFFFFFFFu, a0.w, 16);

    // Full-warp reduce of ksq/qsq.
    #pragma unroll
    for (int m = 16; m >= 1; m >>= 1) {
        ksq += __shfl_xor_sync(0xFFFFFFFFu, ksq, m);
        qsq += __shfl_xor_sync(0xFFFFFFFFu, qsq, m);
    }

    __shared__ float4 s_acc[8][16];
    __shared__ float  s_ksq[8];
    __shared__ float  s_qsq[8];
    const int warp = t >> 5;
    const int lane = t & 31;
    if (lane < 16) s_acc[warp][lane] = a0;
    if (lane == 0) { s_ksq[warp] = ksq; s_qsq[warp] = qsq; }
    __syncthreads();

    float* __restrict__ outp = g_part + (size_t)(bh * NSPLIT + split) * PSTRIDE;
    if (t < 16) {
        float4 a = s_acc[0][t];
        #pragma unroll
        for (int w = 1; w < 8; ++w) {
            float4 b = s_acc[w][t];
            a.x += b.x; a.y += b.y; a.z += b.z; a.w += b.w;
        }
        reinterpret_cast<float4*>(outp)[t] = a;
    } else if (t == 16) {
        float a = 0.f, b = 0.f;
        #pragma unroll
        for (int w = 0; w < 8; ++w) { a += s_ksq[w]; b += s_qsq[w]; }
        outp[64] = a;
        outp[65] = b;
    }
}

// ---------------------------------------------------------------------------
// Kernel 2 (fused combine + broadcast, ~42us @ LTS chip cap):
//   Each CTA recomputes coef[bh][:] from g_part (L2-hot, fixed summation
//   order -> deterministic), stages its 256-row Q slice in smem, then emits
//   a pure streaming-store loop (__stcs float4).
// ---------------------------------------------------------------------------
#define BROWS 256
__global__ __launch_bounds__(256) void broadcast_kernel(
    const float* __restrict__ Q,
    float* __restrict__ out)
{
    const size_t row0 = (size_t)blockIdx.x * BROWS;  // 256 | 16384 -> single bh
    const int    t    = threadIdx.x;
    const int    bh   = (int)(row0 >> 14);

    __shared__ float s_coef[DV];
    __shared__ float s_scale;
    __shared__ float sQ[BROWS];

    // Stage Q slice (1 float per thread, coalesced).
    sQ[t] = Q[row0 + t];

    // Combine partials for this bh (threads 0..63: one e each; thread 64: norms).
    const float* __restrict__ base = g_part + (size_t)bh * NSPLIT * PSTRIDE;
    if (t < DV) {
        float ktv = 0.f;
        #pragma unroll
        for (int s = 0; s < NSPLIT; ++s) ktv += base[(size_t)s * PSTRIDE + t];
        s_coef[t] = ktv;
    } else if (t == DV) {
        float ksq = 0.f, qsq = 0.f;
        #pragma unroll
        for (int s = 0; s < NSPLIT; ++s) {
            ksq += base[(size_t)s * PSTRIDE + 64];
            qsq += base[(size_t)s * PSTRIDE + 65];
        }
        s_scale = 1.0f / (sqrtf(ksq) * sqrtf(qsq));
    }
    __syncthreads();

    const int rg = t >> 4;   // row group 0..15
    const int cg = t & 15;   // float4 column 0..15
    const float scale = s_scale;
    float4 c = reinterpret_cast<const float4*>(s_coef)[cg];
    c.x *= scale; c.y *= scale; c.z *= scale; c.w *= scale;

    // Pure store stream: 16 independent float4 stores per thread.
    #pragma unroll
    for (int ri = 0; ri < BROWS / 16; ++ri) {
        const int    lr  = ri * 16 + rg;
        const size_t row = row0 + lr;
        const float  q   = sQ[lr];
        float4 o;
        o.x = q * c.x;
        o.y = q * c.y;
        o.z = q * c.z;
        o.w = q * c.w;
        __stcs(reinterpret_cast<float4*>(out) + row * 16 + cg, o);
    }
}

// ---------------------------------------------------------------------------
extern "C" void kernel_launch(void* const* d_in, const int* in_sizes, int n_in,
                              void* d_out, int out_size)
{
    const float* Q = (const float*)d_in[0];
    const float* K = (const float*)d_in[1];
    const float* V = (const float*)d_in[2];
    float* out = (float*)d_out;

    reduce_kernel<<<BH * NSPLIT, 256>>>(Q, K, V);
    broadcast_kernel<<<(BH * SEQ) / BROWS, 256>>>(Q, out);
}

// round 17
// speedup vs baseline: 1.0069x; 1.0069x over previous
#include <cuda_runtime.h>

// Fixed shapes: B=8, H=8, S=16384, Dv=64, d_k=1
#define BH      64
#define SEQ     16384
#define DV      64
#define NSPLIT  16
#define CHUNK   (SEQ / NSPLIT)   // 1024 rows per split
#define PSTRIDE 68               // 64 ktv + ksq + qsq, padded to float4 stride

__device__ float g_part[BH * NSPLIT * PSTRIDE];

// ---------------------------------------------------------------------------
// Kernel 1: per-(bh, split) partial reduction (~44us @ LTS chip cap).
//   ktv_part[e] = sum_{s in chunk} K[s] * V[s, e];  + ||K||^2, ||Q||^2 partials
//   K chunk staged in smem; 2 independent __ldcs float4 loads per body,
//   unroll 4 -> 8 loads in flight; dual accumulators.
// ---------------------------------------------------------------------------
__global__ __launch_bounds__(256) void reduce_kernel(
    const float* __restrict__ Q,
    const float* __restrict__ K,
    const float* __restrict__ V)
{
    const int bh    = blockIdx.x / NSPLIT;
    const int split = blockIdx.x % NSPLIT;
    const int t     = threadIdx.x;
    const int colg  = t & 15;   // which float4 of the 64-wide V row
    const int rowg  = t >> 4;   // row offset within a 16-row step

    const float4* __restrict__ Vp4 =
        reinterpret_cast<const float4*>(V + (size_t)bh * SEQ * DV + (size_t)(split * CHUNK) * DV);
    const float4* __restrict__ Kp4 =
        reinterpret_cast<const float4*>(K + bh * SEQ + split * CHUNK);
    const float4* __restrict__ Qp4 =
        reinterpret_cast<const float4*>(Q + bh * SEQ + split * CHUNK);

    __shared__ float sK[CHUNK];

    // Cooperative stage of K chunk + uniform ksq/qsq partials (1 float4 each).
    float4 kv = Kp4[t];
    reinterpret_cast<float4*>(sK)[t] = kv;
    float ksq = kv.x * kv.x + kv.y * kv.y + kv.z * kv.z + kv.w * kv.w;
    float4 qv = Qp4[t];
    float qsq = qv.x * qv.x + qv.y * qv.y + qv.z * qv.z + qv.w * qv.w;
    __syncthreads();

    float4 a0 = make_float4(0.f, 0.f, 0.f, 0.f);
    float4 a1 = make_float4(0.f, 0.f, 0.f, 0.f);

    #pragma unroll 4
    for (int r = rowg; r < CHUNK; r += 32) {
        float  k0 = sK[r];
        float4 v0 = __ldcs(&Vp4[(size_t)r * 16 + colg]);
        float  k1 = sK[r + 16];
        float4 v1 = __ldcs(&Vp4[(size_t)(r + 16) * 16 + colg]);
        a0.x += k0 * v0.x;  a0.y += k0 * v0.y;  a0.z += k0 * v0.z;  a0.w += k0 * v0.w;
        a1.x += k1 * v1.x;  a1.y += k1 * v1.y;  a1.z += k1 * v1.z;  a1.w += k1 * v1.w;
    }
    a0.x += a1.x; a0.y += a1.y; a0.z += a1.z; a0.w += a1.w;

    // Fold the two row-groups within each warp (lane ^ 16 has same colg).
    a0.x += __shfl_xor_sync(0xFFFFFFFFu, a0.x, 16);
    a0.y += __shfl_xor_sync(0xFFFFFFFFu, a0.y, 16);
    a0.z += __shfl_xor_sync(0xFFFFFFFFu, a0.z, 16);
    a0.w += __shfl_xor_sync(0xFFFFFFFFu, a0.w, 16);

    // Full-warp reduce of ksq/qsq.
    #pragma unroll
    for (int m = 16; m >= 1; m >>= 1) {
        ksq += __shfl_xor_sync(0xFFFFFFFFu, ksq, m);
        qsq += __shfl_xor_sync(0xFFFFFFFFu, qsq, m);
    }

    __shared__ float4 s_acc[8][16];
    __shared__ float  s_ksq[8];
    __shared__ float  s_qsq[8];
    const int warp = t >> 5;
    const int lane = t & 31;
    if (lane < 16) s_acc[warp][lane] = a0;
    if (lane == 0) { s_ksq[warp] = ksq; s_qsq[warp] = qsq; }
    __syncthreads();

    float* __restrict__ outp = g_part + (size_t)(bh * NSPLIT + split) * PSTRIDE;
    if (t < 16) {
        float4 a = s_acc[0][t];
        #pragma unroll
        for (int w = 1; w < 8; ++w) {
            float4 b = s_acc[w][t];
            a.x += b.x; a.y += b.y; a.z += b.z; a.w += b.w;
        }
        reinterpret_cast<float4*>(outp)[t] = a;
    } else if (t == 16) {
        float a = 0.f, b = 0.f;
        #pragma unroll
        for (int w = 0; w < 8; ++w) { a += s_ksq[w]; b += s_qsq[w]; }
        outp[64] = a;
        outp[65] = b;
    }
}

// ---------------------------------------------------------------------------
// Kernel 2 (fused combine + broadcast, ~42us @ LTS chip cap):
//   Each CTA recomputes coef[bh][:] from g_part (L2-hot, fixed summation
//   order -> deterministic), stages its 256-row Q slice in smem, then emits
//   a pure streaming-store loop (__stcs float4).
// ---------------------------------------------------------------------------
#define BROWS 256
__global__ __launch_bounds__(256) void broadcast_kernel(
    const float* __restrict__ Q,
    float* __restrict__ out)
{
    const size_t row0 = (size_t)blockIdx.x * BROWS;  // 256 | 16384 -> single bh
    const int    t    = threadIdx.x;
    const int    bh   = (int)(row0 >> 14);

    __shared__ float s_coef[DV];
    __shared__ float s_scale;
    __shared__ float sQ[BROWS];

    // Stage Q slice (1 float per thread, coalesced).
    sQ[t] = Q[row0 + t];

    // Combine partials for this bh (threads 0..63: one e each; thread 64: norms).
    const float* __restrict__ base = g_part + (size_t)bh * NSPLIT * PSTRIDE;
    if (t < DV) {
        float ktv = 0.f;
        #pragma unroll
        for (int s = 0; s < NSPLIT; ++s) ktv += base[(size_t)s * PSTRIDE + t];
        s_coef[t] = ktv;
    } else if (t == DV) {
        float ksq = 0.f, qsq = 0.f;
        #pragma unroll
        for (int s = 0; s < NSPLIT; ++s) {
            ksq += base[(size_t)s * PSTRIDE + 64];
            qsq += base[(size_t)s * PSTRIDE + 65];
        }
        s_scale = 1.0f / (sqrtf(ksq) * sqrtf(qsq));
    }
    __syncthreads();

    const int rg = t >> 4;   // row group 0..15
    const int cg = t & 15;   // float4 column 0..15
    const float scale = s_scale;
    float4 c = reinterpret_cast<const float4*>(s_coef)[cg];
    c.x *= scale; c.y *= scale; c.z *= scale; c.w *= scale;

    // Pure store stream: 16 independent float4 stores per thread.
    #pragma unroll
    for (int ri = 0; ri < BROWS / 16; ++ri) {
        const int    lr  = ri * 16 + rg;
        const size_t row = row0 + lr;
        const float  q   = sQ[lr];
        float4 o;
        o.x = q * c.x;
        o.y = q * c.y;
        o.z = q * c.z;
        o.w = q * c.w;
        __stcs(reinterpret_cast<float4*>(out) + row * 16 + cg, o);
    }
}

// ---------------------------------------------------------------------------
extern "C" void kernel_launch(void* const* d_in, const int* in_sizes, int n_in,
                              void* d_out, int out_size)
{
    const float* Q = (const float*)d_in[0];
    const float* K = (const float*)d_in[1];
    const float* V = (const float*)d_in[2];
    float* out = (float*)d_out;

    reduce_kernel<<<BH * NSPLIT, 256>>>(Q, K, V);
    broadcast_kernel<<<(BH * SEQ) / BROWS, 256>>>(Q, out);
}